// round 6
// baseline (speedup 1.0000x reference)
#include <cuda_runtime.h>

// ISTSimulator: B=65536, V=2, L=200 per-lane recurrence.
// Round 6: geometric-sequence sigmoid. e_{n+1} = e_n * 2^{-a} (1 mul/step)
// with exact per-chunk reseed; exact clamped-ex2a path for saturating chunks.
// D path stays on MUFU (lg2+ex2). 32-step smem staging + coalesced flush.

#define LOG2E_F 1.4426950408889634f
#define SW 33                          // smem row stride (odd -> conflict-free)

__device__ __forceinline__ float ex2a(float x) {
    float r; asm("ex2.approx.ftz.f32 %0, %1;" : "=f"(r) : "f"(x)); return r;
}
__device__ __forceinline__ float lg2a(float x) {
    float r; asm("lg2.approx.f32 %0, %1;" : "=f"(r) : "f"(x)); return r;
}
__device__ __forceinline__ float rcpa(float x) {
    float r; asm("rcp.approx.ftz.f32 %0, %1;" : "=f"(r) : "f"(x)); return r;
}

__global__ void __launch_bounds__(256) ist_geo_kernel(
    const float* __restrict__ in, float* __restrict__ out)
{
    __shared__ float sm[256 * SW];     // 33.8 KB
    int t = threadIdx.x;
    int lane = blockIdx.x * 256 + t;
    int base_lane = blockIdx.x * 256;

    const float* p = in + (size_t)lane * 7;
    float lam  = 0.001f * fmaxf(p[0], 0.0f);
    float nlam = -lam;
    float beta = fmaf(10.0f, fmaxf(p[1], 0.0f), 1.0f);
    float kd   = p[2];
    float mu   = p[3];
    float kf   = p[4];
    float a    = LOG2E_F / p[6];       // sigmoid: g = 1/(1 + 2^(z0 - n*a))
    float z0   = p[5] * a;
    float nkd  = -kd;
    float c    = ex2a(-a);             // geometric ratio (only used on cheap path)

    float u  = 1.0f;                   // u = 1 - D; stays in (0.3, 1]
    float F  = 1e-12f;
    float* sp = &sm[t * SW];

    #pragma unroll 1
    for (int chunk = 0; chunk < 6; ++chunk) {
        int n0 = chunk * 32;
        float zs = fmaf(-(float)n0, a, z0);          // z at chunk start
        float ze = fmaf(-(float)(n0 + 32), a, z0);   // z at chunk end
        // cheap iff e = 2^z never saturates this chunk (monotone in n).
        // Also implies |a| < 7.9 so c is finite and nonzero.
        bool cheap = (fabsf(zs) < 126.0f) && (fabsf(ze) < 126.0f);

        if (cheap) {
            float e = ex2a(zs);                      // exact reseed
            #pragma unroll 8
            for (int j = 0; j < 32; ++j) {
                // D path (MUFU): u' = u - lam * u^beta
                float l  = lg2a(u);
                float pw = ex2a(beta * l);
                u = fmaf(nlam, pw, u);
                // sigmoid: g = 1/(1+e), then advance e geometrically
                float g = rcpa(1.0f + e);
                e *= c;
                // F update
                float q = fmaf(mu, F, 1e-12f);
                F = fminf(fmaxf(fmaf(g, q, F), 0.0f), 1.0f);
                sp[j] = fmaf(kf, F, fmaf(nkd, u, kd));
            }
        } else {
            float jj = 0.0f;
            #pragma unroll 8
            for (int j = 0; j < 32; ++j) {
                float l  = lg2a(u);
                float pw = ex2a(beta * l);
                u = fmaf(nlam, pw, u);
                float z = fmaf(-jj, a, zs);          // exact z, NaN-safe clamp
                z = fminf(fmaxf(z, -126.0f), 126.0f);
                float e = ex2a(z);
                float g = rcpa(1.0f + e);
                float q = fmaf(mu, F, 1e-12f);
                F = fminf(fmaxf(fmaf(g, q, F), 0.0f), 1.0f);
                sp[j] = fmaf(kf, F, fmaf(nkd, u, kd));
                jj += 1.0f;
            }
        }
        __syncthreads();
        // coalesced flush: 256 lanes x 32 steps, float4 per thread
        #pragma unroll
        for (int it = 0; it < 8; ++it) {
            int q4 = it * 1024 + t * 4;
            int r  = q4 >> 5;
            int cc = q4 & 31;
            int sb = r * SW + cc;
            float4 v;
            v.x = sm[sb];
            v.y = sm[sb + 1];
            v.z = sm[sb + 2];
            v.w = sm[sb + 3];
            *reinterpret_cast<float4*>(
                &out[(size_t)(base_lane + r) * 200 + n0 + cc]) = v;
        }
        __syncthreads();
    }

    // remainder: 8 steps (n = 192..199), exact path, direct float4 stores
    {
        float* o = out + (size_t)lane * 200 + 192;
        float nf = 192.0f;
        #pragma unroll
        for (int n4 = 0; n4 < 8; n4 += 4) {
            float4 r;
            float* rv = &r.x;
            #pragma unroll
            for (int j = 0; j < 4; ++j) {
                float l  = lg2a(u);
                float pw = ex2a(beta * l);
                u = fmaf(nlam, pw, u);
                float z = fmaf(-nf, a, z0);
                z = fminf(fmaxf(z, -126.0f), 126.0f);
                float e = ex2a(z);
                float g = rcpa(1.0f + e);
                float q = fmaf(mu, F, 1e-12f);
                F = fminf(fmaxf(fmaf(g, q, F), 0.0f), 1.0f);
                rv[j] = fmaf(kf, F, fmaf(nkd, u, kd));
                nf += 1.0f;
            }
            *reinterpret_cast<float4*>(o + n4) = r;
        }
    }
}

// generic fallback for unexpected shapes
__global__ void __launch_bounds__(256) ist_generic(
    const float* __restrict__ in, float* __restrict__ out, int n_lanes)
{
    int tid = blockIdx.x * blockDim.x + threadIdx.x;
    if (tid >= n_lanes) return;
    const float* p = in + (size_t)tid * 7;
    float lam  = 0.001f * fmaxf(p[0], 0.0f);
    float beta = fmaf(10.0f, fmaxf(p[1], 0.0f), 1.0f);
    float kd = p[2], mu = p[3], kf = p[4];
    float a = LOG2E_F / p[6], z0 = p[5] * a;
    float u = 1.0f, F = 1e-12f, nf = 0.0f;
    float* o = out + (size_t)tid * 200;
    for (int n = 0; n < 200; ++n) {
        float l  = lg2a(fmaxf(u, 1e-12f));
        float pw = ex2a(beta * l);
        u = fminf(fmaxf(fmaf(-lam, pw, u), 0.0f), 1.0f);
        float z = fmaf(-nf, a, z0);
        z = fminf(fmaxf(z, -126.0f), 126.0f);
        float g = rcpa(1.0f + ex2a(z));
        float q = fmaf(mu, F, 1e-12f);
        F = fminf(fmaxf(fmaf(g, q, F), 0.0f), 1.0f);
        o[n] = fmaf(kf, F, fmaf(-kd, u, kd));
        nf += 1.0f;
    }
}

extern "C" void kernel_launch(void* const* d_in, const int* in_sizes, int n_in,
                              void* d_out, int out_size)
{
    const float* in = (const float*)d_in[0];
    float* out = (float*)d_out;
    int n_lanes = in_sizes[0] / 7;
    if (n_lanes % 256 == 0) {
        ist_geo_kernel<<<n_lanes / 256, 256>>>(in, out);
    } else {
        ist_generic<<<(n_lanes + 255) / 256, 256>>>(in, out, n_lanes);
    }
}

// round 7
// speedup vs baseline: 1.4158x; 1.4158x over previous
#include <cuda_runtime.h>

// ISTSimulator: B=65536, V=2, L=200 per-lane recurrence.
// Round 7: R5 math (MUFU: lg2, ex2(pow), rcp; sigmoid exp2 on fma pipe),
// 128-thread blocks (1024 blocks -> max achievable occupancy 27.7 warps/SM),
// 32-step smem staging + coalesced flush, z via literal-j fma (no nf chain).

#define LOG2E_F 1.4426950408889634f
#define MAGICF  12582912.0f            // 1.5 * 2^23
#define KIC     (127 - 0x4B400000)     // exponent splice constant
#define SW 33                          // smem row stride (odd -> conflict-free)
#define BT 128                         // threads per block

__device__ __forceinline__ float ex2a(float x) {
    float r; asm("ex2.approx.ftz.f32 %0, %1;" : "=f"(r) : "f"(x)); return r;
}
__device__ __forceinline__ float lg2a(float x) {
    float r; asm("lg2.approx.f32 %0, %1;" : "=f"(r) : "f"(x)); return r;
}
__device__ __forceinline__ float rcpa(float x) {
    float r; asm("rcp.approx.ftz.f32 %0, %1;" : "=f"(r) : "f"(x)); return r;
}

// fma-pipe 2^z for z in [-126, 126] (caller clamps). rel err ~2.4e-6.
__device__ __forceinline__ float ex2_fma(float z) {
    float m  = z + MAGICF;
    float fi = m - MAGICF;
    float f  = z - fi;                  // f in [-0.5, 0.5]
    float f2 = f * f;
    float f4 = f2 * f2;
    float A = fmaf(0.693147181f,  f, 1.0f);
    float B = fmaf(0.0555041087f, f, 0.240226507f);
    float C = fmaf(0.00133335581f, f, 0.00961812911f);
    float p = fmaf(f2, B, A);
    p = fmaf(f4, C, p);
    unsigned s = (unsigned)(((int)__float_as_uint(m) + KIC) << 23);
    return p * __uint_as_float(s);
}

__global__ void __launch_bounds__(BT) ist_staged_kernel(
    const float* __restrict__ in, float* __restrict__ out)
{
    __shared__ float sm[BT * SW];      // 16.9 KB
    int t = threadIdx.x;
    int base_lane = blockIdx.x * BT;
    int lane = base_lane + t;

    const float* p = in + (size_t)lane * 7;
    float lam  = 0.001f * fmaxf(p[0], 0.0f);
    float nlam = -lam;
    float beta = fmaf(10.0f, fmaxf(p[1], 0.0f), 1.0f);
    float kd   = p[2];
    float mu   = p[3];
    float kf   = p[4];
    float a    = LOG2E_F / p[6];
    float z0   = p[5] * a;
    float na   = -a;
    float nkd  = -kd;

    float u  = 1.0f;                   // u = 1 - D; stays in (0.3, 1]
    float F  = 1e-12f;
    float* sp = &sm[t * SW];

    #pragma unroll 1
    for (int chunk = 0; chunk < 6; ++chunk) {
        int n0 = chunk * 32;
        #pragma unroll 1
        for (int j8 = 0; j8 < 32; j8 += 8) {
            float zb = fmaf((float)(n0 + j8), na, z0);   // exact z at group start
            #pragma unroll
            for (int jj = 0; jj < 8; ++jj) {
                // D path (MUFU): u' = u - lam * 2^(beta * lg2(u))
                float l  = lg2a(u);
                float pw = ex2a(beta * l);
                u = fmaf(nlam, pw, u);

                // sigmoid (fma pipe): g = 1/(1 + 2^z), z = (nc-n)*a, literal jj
                float z = fmaf((float)jj, na, zb);
                z = fminf(fmaxf(z, -126.0f), 126.0f);    // NaN-safe clamp
                float e = ex2_fma(z);
                float g = rcpa(1.0f + e);

                // F = clip((1 + mu*g)*F + eps*g, 0, 1)
                float q = fmaf(mu, F, 1e-12f);
                F = fminf(fmaxf(fmaf(g, q, F), 0.0f), 1.0f);

                sp[j8 + jj] = fmaf(kf, F, fmaf(nkd, u, kd));
            }
        }
        __syncthreads();
        // coalesced flush: BT lanes x 32 steps, float4 per thread
        #pragma unroll
        for (int it = 0; it < 8; ++it) {
            int q4 = it * (BT * 4) + t * 4;   // word index, lane-major
            int r  = q4 >> 5;                 // lane row within block
            int c  = q4 & 31;                 // step within chunk
            int sb = r * SW + c;
            float4 v;
            v.x = sm[sb];
            v.y = sm[sb + 1];
            v.z = sm[sb + 2];
            v.w = sm[sb + 3];
            *reinterpret_cast<float4*>(
                &out[(size_t)(base_lane + r) * 200 + n0 + c]) = v;
        }
        __syncthreads();
    }

    // remainder: 8 steps (n = 192..199), direct float4 stores
    {
        float* o = out + (size_t)lane * 200 + 192;
        float zb = fmaf(192.0f, na, z0);
        #pragma unroll
        for (int n4 = 0; n4 < 8; n4 += 4) {
            float4 r;
            float* rv = &r.x;
            #pragma unroll
            for (int j = 0; j < 4; ++j) {
                float l  = lg2a(u);
                float pw = ex2a(beta * l);
                u = fmaf(nlam, pw, u);
                float z = fmaf((float)(n4 + j), na, zb);
                z = fminf(fmaxf(z, -126.0f), 126.0f);
                float e = ex2_fma(z);
                float g = rcpa(1.0f + e);
                float q = fmaf(mu, F, 1e-12f);
                F = fminf(fmaxf(fmaf(g, q, F), 0.0f), 1.0f);
                rv[j] = fmaf(kf, F, fmaf(nkd, u, kd));
            }
            *reinterpret_cast<float4*>(o + n4) = r;
        }
    }
}

// generic fallback for unexpected shapes
__global__ void __launch_bounds__(256) ist_generic(
    const float* __restrict__ in, float* __restrict__ out, int n_lanes)
{
    int tid = blockIdx.x * blockDim.x + threadIdx.x;
    if (tid >= n_lanes) return;
    const float* p = in + (size_t)tid * 7;
    float lam  = 0.001f * fmaxf(p[0], 0.0f);
    float beta = fmaf(10.0f, fmaxf(p[1], 0.0f), 1.0f);
    float kd = p[2], mu = p[3], kf = p[4];
    float a = LOG2E_F / p[6], z0 = p[5] * a;
    float u = 1.0f, F = 1e-12f, nf = 0.0f;
    float* o = out + (size_t)tid * 200;
    for (int n = 0; n < 200; ++n) {
        float l  = lg2a(fmaxf(u, 1e-12f));
        float pw = ex2a(beta * l);
        u = fminf(fmaxf(fmaf(-lam, pw, u), 0.0f), 1.0f);
        float z = fmaf(-nf, a, z0);
        z = fminf(fmaxf(z, -126.0f), 126.0f);
        float g = rcpa(1.0f + ex2_fma(z));
        float q = fmaf(mu, F, 1e-12f);
        F = fminf(fmaxf(fmaf(g, q, F), 0.0f), 1.0f);
        o[n] = fmaf(kf, F, fmaf(-kd, u, kd));
        nf += 1.0f;
    }
}

extern "C" void kernel_launch(void* const* d_in, const int* in_sizes, int n_in,
                              void* d_out, int out_size)
{
    const float* in = (const float*)d_in[0];
    float* out = (float*)d_out;
    int n_lanes = in_sizes[0] / 7;
    if (n_lanes % BT == 0) {
        ist_staged_kernel<<<n_lanes / BT, BT>>>(in, out);
    } else {
        ist_generic<<<(n_lanes + 255) / 256, 256>>>(in, out, n_lanes);
    }
}

// round 8
// speedup vs baseline: 1.8118x; 1.2797x over previous
#include <cuda_runtime.h>

// ISTSimulator: B=65536, V=2, L=200 per-lane recurrence.
// Round 8: all-MUFU transcendentals (lg2, ex2, ex2, rcp; rt=8 each), no z clamps
// (ex2.approx saturates safely), 15 instr/step. 128-thread blocks, 32-step smem
// staging + coalesced float4 flush (R7 structure).

#define LOG2E_F 1.4426950408889634f
#define SW 33                          // smem row stride (odd -> conflict-free)
#define BT 128                         // threads per block

__device__ __forceinline__ float ex2a(float x) {
    float r; asm("ex2.approx.ftz.f32 %0, %1;" : "=f"(r) : "f"(x)); return r;
}
__device__ __forceinline__ float lg2a(float x) {
    float r; asm("lg2.approx.f32 %0, %1;" : "=f"(r) : "f"(x)); return r;
}
__device__ __forceinline__ float rcpa(float x) {
    float r; asm("rcp.approx.ftz.f32 %0, %1;" : "=f"(r) : "f"(x)); return r;
}

__global__ void __launch_bounds__(BT) ist_staged_kernel(
    const float* __restrict__ in, float* __restrict__ out)
{
    __shared__ float sm[BT * SW];      // 16.9 KB
    int t = threadIdx.x;
    int base_lane = blockIdx.x * BT;
    int lane = base_lane + t;

    const float* p = in + (size_t)lane * 7;
    float lam  = 0.001f * fmaxf(p[0], 0.0f);
    float nlam = -lam;
    float beta = fmaf(10.0f, fmaxf(p[1], 0.0f), 1.0f);
    float kd   = p[2];
    float mu   = p[3];
    float kf   = p[4];
    float a    = LOG2E_F / p[6];       // sigmoid: g = 1/(1 + 2^((nc-n)*a))
    float z0   = p[5] * a;
    float na   = -a;
    float nkd  = -kd;

    float u  = 1.0f;                   // u = 1 - D; stays in (0.3, 1]
    float F  = 1e-12f;
    float* sp = &sm[t * SW];

    #pragma unroll 1
    for (int chunk = 0; chunk < 6; ++chunk) {
        int n0 = chunk * 32;
        float zc = fmaf((float)n0, na, z0);          // z at chunk start (exact)
        #pragma unroll
        for (int j = 0; j < 32; ++j) {
            // D path: u' = u - lam * 2^(beta * lg2(u))   [MUFU lg2 + ex2]
            float l  = lg2a(u);
            float pw = ex2a(beta * l);
            u = fmaf(nlam, pw, u);

            // sigmoid: g = 1/(1 + 2^z), z = (nc-n)*a    [MUFU ex2 + rcp]
            // ex2 saturates (inf/0) for |z| large -> g saturates to 0/1 exactly.
            float z = fmaf((float)j, na, zc);        // literal j: single FFMA
            float e = ex2a(z);
            float g = rcpa(1.0f + e);

            // F = clip((1 + mu*g)*F + eps*g, 0, 1)
            float q = fmaf(mu, F, 1e-12f);
            F = fminf(fmaxf(fmaf(g, q, F), 0.0f), 1.0f);

            sp[j] = fmaf(kf, F, fmaf(nkd, u, kd));
        }
        __syncthreads();
        // coalesced flush: BT lanes x 32 steps, float4 per thread
        #pragma unroll
        for (int it = 0; it < 8; ++it) {
            int q4 = it * (BT * 4) + t * 4;   // word index, lane-major
            int r  = q4 >> 5;                 // lane row within block
            int c  = q4 & 31;                 // step within chunk
            int sb = r * SW + c;
            float4 v;
            v.x = sm[sb];
            v.y = sm[sb + 1];
            v.z = sm[sb + 2];
            v.w = sm[sb + 3];
            *reinterpret_cast<float4*>(
                &out[(size_t)(base_lane + r) * 200 + n0 + c]) = v;
        }
        __syncthreads();
    }

    // remainder: 8 steps (n = 192..199), direct float4 stores
    {
        float* o = out + (size_t)lane * 200 + 192;
        float zc = fmaf(192.0f, na, z0);
        #pragma unroll
        for (int n4 = 0; n4 < 8; n4 += 4) {
            float4 r;
            float* rv = &r.x;
            #pragma unroll
            for (int j = 0; j < 4; ++j) {
                float l  = lg2a(u);
                float pw = ex2a(beta * l);
                u = fmaf(nlam, pw, u);
                float z = fmaf((float)(n4 + j), na, zc);
                float e = ex2a(z);
                float g = rcpa(1.0f + e);
                float q = fmaf(mu, F, 1e-12f);
                F = fminf(fmaxf(fmaf(g, q, F), 0.0f), 1.0f);
                rv[j] = fmaf(kf, F, fmaf(nkd, u, kd));
            }
            *reinterpret_cast<float4*>(o + n4) = r;
        }
    }
}

// generic fallback for unexpected shapes
__global__ void __launch_bounds__(256) ist_generic(
    const float* __restrict__ in, float* __restrict__ out, int n_lanes)
{
    int tid = blockIdx.x * blockDim.x + threadIdx.x;
    if (tid >= n_lanes) return;
    const float* p = in + (size_t)tid * 7;
    float lam  = 0.001f * fmaxf(p[0], 0.0f);
    float beta = fmaf(10.0f, fmaxf(p[1], 0.0f), 1.0f);
    float kd = p[2], mu = p[3], kf = p[4];
    float a = LOG2E_F / p[6], z0 = p[5] * a;
    float u = 1.0f, F = 1e-12f, nf = 0.0f;
    float* o = out + (size_t)tid * 200;
    for (int n = 0; n < 200; ++n) {
        float l  = lg2a(fmaxf(u, 1e-12f));
        float pw = ex2a(beta * l);
        u = fminf(fmaxf(fmaf(-lam, pw, u), 0.0f), 1.0f);
        float z = fmaf(-nf, a, z0);
        float g = rcpa(1.0f + ex2a(z));
        float q = fmaf(mu, F, 1e-12f);
        F = fminf(fmaxf(fmaf(g, q, F), 0.0f), 1.0f);
        o[n] = fmaf(kf, F, fmaf(-kd, u, kd));
        nf += 1.0f;
    }
}

extern "C" void kernel_launch(void* const* d_in, const int* in_sizes, int n_in,
                              void* d_out, int out_size)
{
    const float* in = (const float*)d_in[0];
    float* out = (float*)d_out;
    int n_lanes = in_sizes[0] / 7;
    if (n_lanes % BT == 0) {
        ist_staged_kernel<<<n_lanes / BT, BT>>>(in, out);
    } else {
        ist_generic<<<(n_lanes + 255) / 256, 256>>>(in, out, n_lanes);
    }
}